// round 1
// baseline (speedup 1.0000x reference)
#include <cuda_runtime.h>
#include <cstdint>

#define BATCHES 8
#define NB      32768
#define NCLS    81
#define PRE_K   2048
#define CAP     4096
#define MAX_OUT 200

// ---------------- scratch (device globals; no allocation allowed) ----------
__device__ unsigned long long g_keys[BATCHES * NB];      // (score_bits<<32)|(NB-1-idx), 0 if invalid
__device__ unsigned char      g_cat [BATCHES * NB];      // argmax class
__device__ unsigned long long g_topkeys[BATCHES * PRE_K];// sorted desc per batch

// ---------------- kernel 1: per-anchor max/argmax over 81 classes ----------
__global__ void __launch_bounds__(256)
score_kernel(const float* __restrict__ confs) {
    int gwarp = (blockIdx.x * blockDim.x + threadIdx.x) >> 5;  // = b*NB + n
    int lane  = threadIdx.x & 31;
    const float* c = confs + (size_t)gwarp * NCLS;

    float m = -1.0f; int mi = 0;
    #pragma unroll
    for (int j = lane; j < NCLS; j += 32) {
        float v = __ldg(c + j);
        if (v > m) { m = v; mi = j; }       // per-lane ascending j: '>' keeps first max
    }
    #pragma unroll
    for (int off = 16; off; off >>= 1) {
        float ov = __shfl_down_sync(0xffffffffu, m, off);
        int   oi = __shfl_down_sync(0xffffffffu, mi, off);
        if (ov > m || (ov == m && oi < mi)) { m = ov; mi = oi; }
    }
    if (lane == 0) {
        bool valid = (m > 0.05f) && (mi != 0);
        unsigned int n = (unsigned int)gwarp & (NB - 1);
        unsigned long long key = 0ULL;
        if (valid)
            key = (((unsigned long long)__float_as_uint(m)) << 32)
                | (unsigned long long)(NB - 1u - n);
        g_keys[gwarp] = key;
        g_cat[gwarp]  = (unsigned char)mi;
    }
}

// ---------------- kernel 2: per-batch exact top-2048 (radix-select + sort) --
__global__ void __launch_bounds__(1024)
select_topk_kernel() {
    const int b = blockIdx.x;
    const unsigned long long* keys = g_keys + (size_t)b * NB;

    __shared__ unsigned int       hist[2048];
    __shared__ unsigned long long cand[CAP];
    __shared__ unsigned int       wsum[32];
    __shared__ unsigned int       sh_t, sh_above, sh_cnt;

    const int tid  = threadIdx.x;
    const int lane = tid & 31;
    const int warp = tid >> 5;

    unsigned int prefix = 0;
    int          prefshift = 32;           // bits consumed so far live at [31:prefshift]
    unsigned int above = 0;                // count strictly above current threshold prefix

    const int shifts[3]  = {21, 10, 0};
    const int bitsArr[3] = {11, 11, 10};

    for (int p = 0; p < 3; p++) {
        const int bins = 1 << bitsArr[p];
        for (int i = tid; i < bins; i += 1024) hist[i] = 0;
        __syncthreads();

        // histogram with warp-aggregated atomics (scores cluster in few buckets)
        for (int i = tid; i < NB; i += 1024) {
            unsigned int sb = (unsigned int)(keys[i] >> 32);
            bool cond;
            if (prefshift >= 32) cond = true;
            else cond = ((sb >> prefshift) == prefix);
            unsigned int bucket = cond ? ((sb >> shifts[p]) & (unsigned)(bins - 1))
                                       : 0xFFFFFFFFu;
            unsigned mm = __match_any_sync(0xffffffffu, bucket);
            if (bucket != 0xFFFFFFFFu && (__ffs(mm) - 1) == lane)
                atomicAdd(&hist[bucket], (unsigned)__popc(mm));
        }
        __syncthreads();

        // find boundary bucket from the TOP via parallel suffix (reversed prefix) scan
        const unsigned int K = PRE_K - above;   // >= 1 always
        const int chunk = bins >> 10;           // 2 or 1
        const int base_r = tid * (chunk ? chunk : 1);
        unsigned int v0 = 0, v1 = 0;
        if (chunk >= 1 && base_r < bins) v0 = hist[bins - 1 - base_r];
        if (chunk == 2)                  v1 = hist[bins - 1 - (base_r + 1)];
        unsigned int lsum = v0 + v1;
        unsigned int s = lsum;
        #pragma unroll
        for (int off = 1; off < 32; off <<= 1) {
            unsigned int t = __shfl_up_sync(0xffffffffu, s, off);
            if (lane >= off) s += t;
        }
        if (lane == 31) wsum[warp] = s;
        __syncthreads();
        if (warp == 0) {
            unsigned int ws = wsum[lane];
            #pragma unroll
            for (int off = 1; off < 32; off <<= 1) {
                unsigned int t = __shfl_up_sync(0xffffffffu, ws, off);
                if (lane >= off) ws += t;
            }
            wsum[lane] = ws;
        }
        __syncthreads();
        unsigned int excl = s - lsum + (warp ? wsum[warp - 1] : 0u);
        unsigned int run = excl;
        if (run < K && run + v0 >= K) { sh_t = (unsigned)(bins - 1 - base_r); sh_above = run; }
        run += v0;
        if (chunk == 2) {
            if (run < K && run + v1 >= K) { sh_t = (unsigned)(bins - 2 - base_r); sh_above = run; }
        }
        __syncthreads();
        above += sh_above;
        prefix = (prefix << bitsArr[p]) | sh_t;
        prefshift = shifts[p];
        __syncthreads();
    }
    const unsigned int Tsb = prefix;  // full 32-bit score-bits of 2048th largest

    // compaction: all items with sb >= Tsb (and valid) into shared, warp-aggregated
    if (tid == 0) sh_cnt = 0;
    __syncthreads();
    for (int i = tid; i < NB; i += 1024) {
        unsigned long long k = keys[i];
        unsigned int sb = (unsigned int)(k >> 32);
        bool c = (sb >= Tsb) && (sb != 0u);
        unsigned bal = __ballot_sync(0xffffffffu, c);
        if (bal) {
            int leader = __ffs(bal) - 1;
            unsigned int basep = 0;
            if (lane == leader) basep = atomicAdd(&sh_cnt, (unsigned)__popc(bal));
            basep = __shfl_sync(0xffffffffu, basep, leader);
            if (c) {
                unsigned int pos = basep + (unsigned)__popc(bal & ((1u << lane) - 1u));
                if (pos < CAP) cand[pos] = k;
            }
        }
    }
    __syncthreads();
    unsigned int cnt = sh_cnt; if (cnt > CAP) cnt = CAP;
    for (int i = tid; i < CAP; i += 1024) if (i >= (int)cnt) cand[i] = 0ULL;
    __syncthreads();

    // bitonic sort descending, n = CAP = 4096
    for (int k = 2; k <= CAP; k <<= 1) {
        for (int j = k >> 1; j > 0; j >>= 1) {
            #pragma unroll
            for (int s0 = 0; s0 < CAP; s0 += 1024) {
                int i = s0 + tid;
                int l = i ^ j;
                if (l > i) {
                    unsigned long long a = cand[i], bb = cand[l];
                    bool up = ((i & k) == 0);   // descending overall
                    if ((a < bb) == up) { cand[i] = bb; cand[l] = a; }
                }
            }
            __syncthreads();
        }
    }
    for (int i = tid; i < PRE_K; i += 1024)
        g_topkeys[(size_t)b * PRE_K + i] = cand[i];
}

// ---------------- kernel 3: streaming greedy NMS + output --------------------
__global__ void __launch_bounds__(256)
nms_kernel(const float* __restrict__ boxes, float* __restrict__ out, int write_cats) {
    const int b = blockIdx.x;
    __shared__ float sx1[PRE_K], sy1[PRE_K], sx2[PRE_K], sy2[PRE_K], sarea[PRE_K];
    __shared__ short scls[PRE_K];
    __shared__ short kept[MAX_OUT];
    __shared__ int   sh_nk;

    const unsigned long long* tk  = g_topkeys + (size_t)b * PRE_K;
    const float*              bxs = boxes + (size_t)b * NB * 4;
    const unsigned char*      cats = g_cat + (size_t)b * NB;
    const int tid = threadIdx.x;

    for (int i = tid; i < PRE_K; i += 256) {
        unsigned long long k = tk[i];
        if (k == 0ULL) {
            scls[i] = -1; sx1[i] = sy1[i] = sx2[i] = sy2[i] = 0.f; sarea[i] = 0.f;
        } else {
            int idx = (NB - 1) - (int)(unsigned int)k;
            float4 bb = *(const float4*)(bxs + (size_t)idx * 4);
            sx1[i] = bb.x; sy1[i] = bb.y; sx2[i] = bb.z; sy2[i] = bb.w;
            sarea[i] = fmaxf(bb.z - bb.x, 0.f) * fmaxf(bb.w - bb.y, 0.f);
            scls[i]  = (short)cats[idx];
        }
    }
    __syncthreads();

    // one warp does the order-exact greedy scan; early exit at MAX_OUT kept
    if (tid < 32) {
        const int lane = tid;
        int nk = 0;
        for (int i = 0; i < PRE_K && nk < MAX_OUT; i++) {
            short ci = scls[i];
            if (ci < 0) continue;
            float x1 = sx1[i], y1 = sy1[i], x2 = sx2[i], y2 = sy2[i], ar = sarea[i];
            bool sup = false;
            for (int k0 = lane; k0 < nk; k0 += 32) {
                int j = kept[k0];
                if (scls[j] == ci) {
                    float ix1 = fmaxf(x1, sx1[j]);
                    float iy1 = fmaxf(y1, sy1[j]);
                    float ix2 = fminf(x2, sx2[j]);
                    float iy2 = fminf(y2, sy2[j]);
                    float inter = fmaxf(ix2 - ix1, 0.f) * fmaxf(iy2 - iy1, 0.f);
                    float uni   = ar + sarea[j] - inter;
                    if (inter / fmaxf(uni, 1e-9f) > 0.5f) sup = true;
                }
            }
            sup = __any_sync(0xffffffffu, sup);
            if (!sup) {
                if (lane == 0) kept[nk] = (short)i;
                __syncwarp();
                nk++;
            }
        }
        if (lane == 0) sh_nk = nk;
    }
    __syncthreads();

    const int nk = sh_nk;
    float* out5 = out + (size_t)b * MAX_OUT * 5;
    float* ocat = out + (size_t)BATCHES * MAX_OUT * 5 + (size_t)b * MAX_OUT;
    for (int k0 = tid; k0 < MAX_OUT; k0 += 256) {
        float vx1 = 0, vy1 = 0, vx2 = 0, vy2 = 0, vs = 0, vc = 0;
        if (k0 < nk) {
            int i = kept[k0];
            vx1 = sx1[i]; vy1 = sy1[i]; vx2 = sx2[i]; vy2 = sy2[i];
            vs  = __uint_as_float((unsigned int)(tk[i] >> 32));
            vc  = (float)scls[i];
        }
        out5[k0 * 5 + 0] = vx1;
        out5[k0 * 5 + 1] = vy1;
        out5[k0 * 5 + 2] = vx2;
        out5[k0 * 5 + 3] = vy2;
        out5[k0 * 5 + 4] = vs;
        if (write_cats) ocat[k0] = vc;
    }
}

// ---------------- launch ----------------------------------------------------
extern "C" void kernel_launch(void* const* d_in, const int* in_sizes, int n_in,
                              void* d_out, int out_size) {
    // metadata order: boxes_ltrb [8,32768,4], confs [8,32768,81]; pick by size defensively
    const float* boxes = (const float*)d_in[0];
    const float* confs = (const float*)d_in[1];
    if (n_in >= 2 && in_sizes[0] > in_sizes[1]) {
        boxes = (const float*)d_in[1];
        confs = (const float*)d_in[0];
    }
    float* out = (float*)d_out;

    // zero-fill output (poisoned 0xAA); memset node is graph-capturable
    cudaMemsetAsync(d_out, 0, (size_t)out_size * sizeof(float), 0);

    const int total_warps = BATCHES * NB;            // 262144
    score_kernel<<<total_warps * 32 / 256, 256>>>(confs);
    select_topk_kernel<<<BATCHES, 1024>>>();
    int write_cats = (out_size >= BATCHES * MAX_OUT * 6) ? 1 : 0;
    nms_kernel<<<BATCHES, 256>>>(boxes, out, write_cats);
}

// round 2
// speedup vs baseline: 1.2582x; 1.2582x over previous
#include <cuda_runtime.h>
#include <cstdint>

#define BATCHES 8
#define NB      32768
#define NCLS    81
#define PRE_K   2048
#define CAP     4096
#define MAX_OUT 200
#define SB_ANCH 128   // anchors per score block

// ---------------- scratch (device globals; no allocation allowed) ----------
__device__ unsigned long long g_keys[BATCHES * NB];      // (score_bits<<32)|(NB-1-idx), 0 if invalid
__device__ unsigned char      g_cat [BATCHES * NB];      // argmax class
__device__ unsigned long long g_topkeys[BATCHES * PRE_K];// sorted desc per batch

// ---------------- kernel 1: per-anchor max/argmax over 81 classes ----------
// smem-staged: coalesced float4 gmem->smem, then thread-per-anchor scan.
__global__ void __launch_bounds__(SB_ANCH)
score_kernel(const float* __restrict__ confs) {
    __shared__ float s[SB_ANCH * NCLS];   // 41472 B

    const int a0 = blockIdx.x * SB_ANCH;  // global anchor base (over B*NB)
    // stage: contiguous SB_ANCH*81 floats, 16B-aligned block base
    const float4* src = (const float4*)(confs + (size_t)a0 * NCLS);
    float4* dst = (float4*)s;
    const int n4 = SB_ANCH * NCLS / 4;    // 2592
    #pragma unroll 4
    for (int i = threadIdx.x; i < n4; i += SB_ANCH) dst[i] = src[i];
    __syncthreads();

    const float* row = s + threadIdx.x * NCLS;
    float m = -1.0f; int mi = 0;
    #pragma unroll
    for (int j = 0; j < NCLS; j++) {
        float v = row[j];
        if (v > m) { m = v; mi = j; }     // ascending j + '>' keeps first max
    }
    const int a = a0 + threadIdx.x;
    bool valid = (m > 0.05f) && (mi != 0);
    unsigned int n = (unsigned int)a & (NB - 1);
    unsigned long long key = 0ULL;
    if (valid)
        key = (((unsigned long long)__float_as_uint(m)) << 32)
            | (unsigned long long)(NB - 1u - n);
    g_keys[a] = key;
    g_cat[a]  = (unsigned char)mi;
}

// ---------------- kernel 2: per-batch exact top-2048 (radix-select + sort) --
__global__ void __launch_bounds__(1024)
select_topk_kernel() {
    const int b = blockIdx.x;
    const unsigned long long* keys = g_keys + (size_t)b * NB;

    __shared__ unsigned int       hist[2048];
    __shared__ unsigned long long cand[CAP];
    __shared__ unsigned int       wsum[32];
    __shared__ unsigned int       sh_t, sh_above, sh_cnt;

    const int tid  = threadIdx.x;
    const int lane = tid & 31;
    const int warp = tid >> 5;

    unsigned int prefix = 0;
    int          prefshift = 32;
    unsigned int above = 0;

    const int shifts[3]  = {21, 10, 0};
    const int bitsArr[3] = {11, 11, 10};

    for (int p = 0; p < 3; p++) {
        const int bins = 1 << bitsArr[p];
        for (int i = tid; i < bins; i += 1024) hist[i] = 0;
        __syncthreads();

        for (int i = tid; i < NB; i += 1024) {
            unsigned int sb = (unsigned int)(keys[i] >> 32);
            bool cond;
            if (prefshift >= 32) cond = true;
            else cond = ((sb >> prefshift) == prefix);
            unsigned int bucket = cond ? ((sb >> shifts[p]) & (unsigned)(bins - 1))
                                       : 0xFFFFFFFFu;
            unsigned mm = __match_any_sync(0xffffffffu, bucket);
            if (bucket != 0xFFFFFFFFu && (__ffs(mm) - 1) == lane)
                atomicAdd(&hist[bucket], (unsigned)__popc(mm));
        }
        __syncthreads();

        const unsigned int K = PRE_K - above;
        const int chunk = bins >> 10;           // 2 or 1
        const int base_r = tid * (chunk ? chunk : 1);
        unsigned int v0 = 0, v1 = 0;
        if (chunk >= 1 && base_r < bins) v0 = hist[bins - 1 - base_r];
        if (chunk == 2)                  v1 = hist[bins - 1 - (base_r + 1)];
        unsigned int lsum = v0 + v1;
        unsigned int s = lsum;
        #pragma unroll
        for (int off = 1; off < 32; off <<= 1) {
            unsigned int t = __shfl_up_sync(0xffffffffu, s, off);
            if (lane >= off) s += t;
        }
        if (lane == 31) wsum[warp] = s;
        __syncthreads();
        if (warp == 0) {
            unsigned int ws = wsum[lane];
            #pragma unroll
            for (int off = 1; off < 32; off <<= 1) {
                unsigned int t = __shfl_up_sync(0xffffffffu, ws, off);
                if (lane >= off) ws += t;
            }
            wsum[lane] = ws;
        }
        __syncthreads();
        unsigned int excl = s - lsum + (warp ? wsum[warp - 1] : 0u);
        unsigned int run = excl;
        if (run < K && run + v0 >= K) { sh_t = (unsigned)(bins - 1 - base_r); sh_above = run; }
        run += v0;
        if (chunk == 2) {
            if (run < K && run + v1 >= K) { sh_t = (unsigned)(bins - 2 - base_r); sh_above = run; }
        }
        __syncthreads();
        above += sh_above;
        prefix = (prefix << bitsArr[p]) | sh_t;
        prefshift = shifts[p];
        __syncthreads();
    }
    const unsigned int Tsb = prefix;

    if (tid == 0) sh_cnt = 0;
    __syncthreads();
    for (int i = tid; i < NB; i += 1024) {
        unsigned long long k = keys[i];
        unsigned int sb = (unsigned int)(k >> 32);
        bool c = (sb >= Tsb) && (sb != 0u);
        unsigned bal = __ballot_sync(0xffffffffu, c);
        if (bal) {
            int leader = __ffs(bal) - 1;
            unsigned int basep = 0;
            if (lane == leader) basep = atomicAdd(&sh_cnt, (unsigned)__popc(bal));
            basep = __shfl_sync(0xffffffffu, basep, leader);
            if (c) {
                unsigned int pos = basep + (unsigned)__popc(bal & ((1u << lane) - 1u));
                if (pos < CAP) cand[pos] = k;
            }
        }
    }
    __syncthreads();
    unsigned int cnt = sh_cnt; if (cnt > CAP) cnt = CAP;
    for (int i = tid; i < CAP; i += 1024) if (i >= (int)cnt) cand[i] = 0ULL;
    __syncthreads();

    for (int k = 2; k <= CAP; k <<= 1) {
        for (int j = k >> 1; j > 0; j >>= 1) {
            #pragma unroll
            for (int s0 = 0; s0 < CAP; s0 += 1024) {
                int i = s0 + tid;
                int l = i ^ j;
                if (l > i) {
                    unsigned long long a = cand[i], bb = cand[l];
                    bool up = ((i & k) == 0);
                    if ((a < bb) == up) { cand[i] = bb; cand[l] = a; }
                }
            }
            __syncthreads();
        }
    }
    for (int i = tid; i < PRE_K; i += 1024)
        g_topkeys[(size_t)b * PRE_K + i] = cand[i];
}

// ---------------- kernel 3: greedy NMS with register-resident kept list ----
__global__ void __launch_bounds__(256)
nms_kernel(const float* __restrict__ boxes, float* __restrict__ out, int write_cats) {
    const int b = blockIdx.x;
    __shared__ float4 scand[PRE_K];     // 32 KB: x1,y1,x2,y2
    __shared__ short  scls[PRE_K];      // 4 KB
    __shared__ short  kept_idx[MAX_OUT];
    __shared__ int    sh_nk;

    const unsigned long long* tk   = g_topkeys + (size_t)b * PRE_K;
    const float*              bxs  = boxes + (size_t)b * NB * 4;
    const unsigned char*      cats = g_cat + (size_t)b * NB;
    const int tid = threadIdx.x;

    for (int i = tid; i < PRE_K; i += 256) {
        unsigned long long k = tk[i];
        if (k == 0ULL) {
            scls[i] = -1;
            scand[i] = make_float4(0.f, 0.f, 0.f, 0.f);
        } else {
            int idx = (NB - 1) - (int)(unsigned int)k;
            scand[i] = *(const float4*)(bxs + (size_t)idx * 4);
            scls[i]  = (short)cats[idx];
        }
    }
    __syncthreads();

    // warp 0: order-exact greedy scan; kept boxes live in registers (7 slots/lane)
    if (tid < 32) {
        const int lane = tid;
        float kx1[7], ky1[7], kx2[7], ky2[7], kar[7];
        short kcl[7];
        int nk = 0;
        for (int i = 0; i < PRE_K && nk < MAX_OUT; i++) {
            short ci = scls[i];            // broadcast smem read (uniform)
            if (ci < 0) break;             // sorted desc: zero tail
            float4 bb = scand[i];          // broadcast LDS.128
            float ar = fmaxf(bb.z - bb.x, 0.f) * fmaxf(bb.w - bb.y, 0.f);
            bool sup = false;
            const int ns = (nk + 31) >> 5; // warp-uniform trip count
            #pragma unroll
            for (int s = 0; s < 7; s++) {
                if (s >= ns) break;
                if ((s * 32 + lane) < nk && kcl[s] == ci) {
                    float ix1 = fmaxf(bb.x, kx1[s]);
                    float iy1 = fmaxf(bb.y, ky1[s]);
                    float ix2 = fminf(bb.z, kx2[s]);
                    float iy2 = fminf(bb.w, ky2[s]);
                    float inter = fmaxf(ix2 - ix1, 0.f) * fmaxf(iy2 - iy1, 0.f);
                    float uni   = ar + kar[s] - inter;
                    if (inter / fmaxf(uni, 1e-9f) > 0.5f) sup = true;
                }
            }
            sup = __any_sync(0xffffffffu, sup);
            if (!sup) {
                int slot = nk >> 5;
                if ((nk & 31) == lane) {
                    #pragma unroll
                    for (int s = 0; s < 7; s++) {
                        if (slot == s) {
                            kx1[s] = bb.x; ky1[s] = bb.y;
                            kx2[s] = bb.z; ky2[s] = bb.w;
                            kar[s] = ar;   kcl[s] = ci;
                        }
                    }
                }
                if (lane == 0) kept_idx[nk] = (short)i;
                nk++;
            }
        }
        if (lane == 0) sh_nk = nk;
    }
    __syncthreads();

    const int nk = sh_nk;
    float* out5 = out + (size_t)b * MAX_OUT * 5;
    float* ocat = out + (size_t)BATCHES * MAX_OUT * 5 + (size_t)b * MAX_OUT;
    for (int k0 = tid; k0 < MAX_OUT; k0 += 256) {
        float vx1 = 0, vy1 = 0, vx2 = 0, vy2 = 0, vs = 0, vc = 0;
        if (k0 < nk) {
            int i = kept_idx[k0];
            float4 bb = scand[i];
            vx1 = bb.x; vy1 = bb.y; vx2 = bb.z; vy2 = bb.w;
            vs  = __uint_as_float((unsigned int)(tk[i] >> 32));
            vc  = (float)scls[i];
        }
        out5[k0 * 5 + 0] = vx1;
        out5[k0 * 5 + 1] = vy1;
        out5[k0 * 5 + 2] = vx2;
        out5[k0 * 5 + 3] = vy2;
        out5[k0 * 5 + 4] = vs;
        if (write_cats) ocat[k0] = vc;
    }
}

// ---------------- launch ----------------------------------------------------
extern "C" void kernel_launch(void* const* d_in, const int* in_sizes, int n_in,
                              void* d_out, int out_size) {
    const float* boxes = (const float*)d_in[0];
    const float* confs = (const float*)d_in[1];
    if (n_in >= 2 && in_sizes[0] > in_sizes[1]) {
        boxes = (const float*)d_in[1];
        confs = (const float*)d_in[0];
    }
    float* out = (float*)d_out;

    cudaMemsetAsync(d_out, 0, (size_t)out_size * sizeof(float), 0);

    score_kernel<<<(BATCHES * NB) / SB_ANCH, SB_ANCH>>>(confs);
    select_topk_kernel<<<BATCHES, 1024>>>();
    int write_cats = (out_size >= BATCHES * MAX_OUT * 6) ? 1 : 0;
    nms_kernel<<<BATCHES, 256>>>(boxes, out, write_cats);
}